// round 3
// baseline (speedup 1.0000x reference)
#include <cuda_runtime.h>

// Shapes (this instance): B=2048, L=196, M=16, NBL=10. Derived from in_sizes.
#define MAXSITES 256          // >= L-2 (=194)
#define MAXB     4096         // >= B   (=2048)
#define MAXL     256          // >= L   (=196)

// Pre-paired site tensors for f32x2 math:
//   mat4[s][m*8+q] = {A0[m][q], A0[m][q+8], A1[m][q], A1[m][q+8]}
// L: forward order; R: reversed + transposed (right sweep runs forward form).
__device__ float4 g_mat4L[MAXSITES * 128];
__device__ float4 g_mat4R[MAXSITES * 128];
__device__ float  g_left [MAXB * 16];
__device__ float  g_right[MAXB * 16];

// ---------------------------------------------------------------------------
// f32x2 helpers (packed fp32 pairs in b64 regs — Blackwell FFMA2 path)
// ---------------------------------------------------------------------------
__device__ __forceinline__ unsigned long long pack2(float x, float y) {
    unsigned long long r;
    asm("mov.b64 %0, {%1,%2};" : "=l"(r) : "f"(x), "f"(y));
    return r;
}
__device__ __forceinline__ void unpack2(unsigned long long v, float& x, float& y) {
    asm("mov.b64 {%0,%1}, %2;" : "=f"(x), "=f"(y) : "l"(v));
}
__device__ __forceinline__ void fma2(unsigned long long& d,
                                     unsigned long long a, unsigned long long b) {
    asm("fma.rn.f32x2 %0, %1, %2, %0;" : "+l"(d) : "l"(a), "l"(b));
}
__device__ __forceinline__ unsigned long long mul2(unsigned long long a,
                                                   unsigned long long b) {
    unsigned long long d;
    asm("mul.rn.f32x2 %0, %1, %2;" : "=l"(d) : "l"(a), "l"(b));
    return d;
}
__device__ __forceinline__ unsigned long long add2(unsigned long long a,
                                                   unsigned long long b) {
    unsigned long long d;
    asm("add.rn.f32x2 %0, %1, %2;" : "=l"(d) : "l"(a), "l"(b));
    return d;
}

// ---------------------------------------------------------------------------
// cp.async helpers
// ---------------------------------------------------------------------------
__device__ __forceinline__ void cpasync16(unsigned dst, const void* src) {
    asm volatile("cp.async.cg.shared.global [%0], [%1], 16;\n"
                 :: "r"(dst), "l"(src) : "memory");
}
__device__ __forceinline__ void cpcommit() {
    asm volatile("cp.async.commit_group;\n" ::: "memory");
}
template<int N> __device__ __forceinline__ void cpwait() {
    asm volatile("cp.async.wait_group %0;\n" :: "n"(N) : "memory");
}

// ---------------------------------------------------------------------------
// Kernel 1: repack A_mid (Lm2,2,16,16) into paired float4 layout. 2 sites/block,
// 8 independent loads per thread (MLP 8) to cover DRAM latency.
// ---------------------------------------------------------------------------
__global__ void __launch_bounds__(256)
prep_kernel(const float* __restrict__ A_mid, int Lm2) {
    int t = threadIdx.x;
    int s = blockIdx.x * 2 + (t >> 7);
    if (s >= Lm2) return;
    int e = t & 127;            // m*8+q
    int m = e >> 3, q = e & 7;
    const float* A0 = A_mid + s * 512;
    const float* A1 = A0 + 256;
    float4 L4 = make_float4(A0[m * 16 + q], A0[m * 16 + q + 8],
                            A1[m * 16 + q], A1[m * 16 + q + 8]);
    float4 R4 = make_float4(A0[q * 16 + m], A0[(q + 8) * 16 + m],
                            A1[q * 16 + m], A1[(q + 8) * 16 + m]);
    g_mat4L[s * 128 + e] = L4;
    g_mat4R[(Lm2 - 1 - s) * 128 + e] = R4;
}

// ---------------------------------------------------------------------------
// Kernel 2: lockstep chain contraction, f32x2 math.
// Block = 128 thr = 16 chains (quarter-warp per chain; lane q=lane&7 owns
// components n0=q, n1=q+8). Matrices staged via 3-deep cp.async ring; x-inputs
// staged once; v exchanged pre-splatted in smem. One barrier per site.
// ---------------------------------------------------------------------------
__global__ void __launch_bounds__(128)
chain_kernel(const float* __restrict__ inputs,
             const float* __restrict__ A_left,
             const float* __restrict__ A_right,
             const int*   __restrict__ pos_ptr,
             int B, int L) {
    __shared__ float4 ring[3][128];     // 3 x 2KB matrix ring
    __shared__ float2 sV[16][18];       // per-chain splatted v, padded rows
    __shared__ float2 sX[16][MAXL];     // per-chain input series

    int tid  = threadIdx.x;
    int lane = tid & 31;
    int w    = tid >> 5;
    int q    = lane & 7;
    int lc   = w * 4 + (lane >> 3);     // local chain 0..15

    int pos = __ldg(pos_ptr);
    int nLeftBlocks = B >> 4;
    bool isLeft = (blockIdx.x < (unsigned)nLeftBlocks);
    int blk = isLeft ? blockIdx.x : blockIdx.x - nLeftBlocks;
    int c   = blk * 16 + lc;            // global sample
    int nsites = isLeft ? pos : (L - 2 - pos);

    const float4* mats  = isLeft ? g_mat4L : g_mat4R;
    const float*  seedA = isLeft ? A_left  : A_right;
    const float2* in2   = (const float2*)inputs;     // (B,L) float2
    int seedSite = isLeft ? 0 : (L - 1);

    unsigned rbase = (unsigned)__cvta_generic_to_shared(&ring[0][0]);
    unsigned xbase = (unsigned)__cvta_generic_to_shared(&sX[0][0]);

    // ---- stage sX (whole series for 16 chains) + mat site0 : group 0 ----
    {
        int chunksPerChain = L >> 1;                 // 16B chunks (L even)
        int nOps = 16 * chunksPerChain;
        for (int i = tid; i < nOps; i += 128) {
            int ch  = i / chunksPerChain;
            int off = i - ch * chunksPerChain;
            const char* src = (const char*)(in2 + (blk * 16 + ch) * L) + off * 16;
            cpasync16(xbase + ch * (MAXL * 8) + off * 16, src);
        }
        if (nsites > 0)
            cpasync16(rbase + tid * 16, (const char*)mats + tid * 16);
        cpcommit();                                   // group 0
        if (nsites > 1)
            cpasync16(rbase + 2048 + tid * 16, (const char*)(mats + 128) + tid * 16);
        cpcommit();                                   // group 1
    }

    cpwait<1>();          // group 0 (sX + mat0) complete
    __syncthreads();

    // ---- seed: v[n] = x0*Aseed[0][n] + x1*Aseed[1][n] ----
    int n0 = q, n1 = q + 8;
    float2 xs = sX[lc][seedSite];
    float v0 = fmaf(xs.y, __ldg(seedA + 16 + n0), xs.x * __ldg(seedA + n0));
    float v1 = fmaf(xs.y, __ldg(seedA + 16 + n1), xs.x * __ldg(seedA + n1));
    sV[lc][n0] = make_float2(v0, v0);
    sV[lc][n1] = make_float2(v1, v1);

    int stage = 0, stage2 = 2;
    for (int s = 0; s < nsites; ++s) {
        if (s > 0) { cpwait<1>(); __syncthreads(); }
        if (s + 2 < nsites)
            cpasync16(rbase + stage2 * 2048 + tid * 16,
                      (const char*)(mats + (s + 2) * 128) + tid * 16);
        cpcommit();

        // v splats: 16 components x {v,v} = 8 x LDS.128 (broadcast per chain)
        const ulonglong2* vp = (const ulonglong2*)&sV[lc][0];
        unsigned long long vs[16];
#pragma unroll
        for (int j = 0; j < 8; ++j) {
            ulonglong2 t = vp[j];
            vs[2 * j]     = t.x;
            vs[2 * j + 1] = t.y;
        }

        int xsite = isLeft ? (1 + s) : (L - 2 - s);
        float2 x = sX[lc][xsite];
        unsigned long long xx0 = pack2(x.x, x.x);
        unsigned long long xx1 = pack2(x.y, x.y);

        const ulonglong2* mp = (const ulonglong2*)&ring[stage][0] + q;
        unsigned long long aA0 = 0ull, aA1 = 0ull, aB0 = 0ull, aB1 = 0ull;
#pragma unroll
        for (int m = 0; m < 16; m += 2) {
            ulonglong2 ma = mp[m * 8];          // {A0 pair, A1 pair} for m
            ulonglong2 mb = mp[(m + 1) * 8];    // ... for m+1
            fma2(aA0, vs[m],     ma.x);
            fma2(aB0, vs[m],     ma.y);
            fma2(aA1, vs[m + 1], mb.x);
            fma2(aB1, vs[m + 1], mb.y);
        }
        unsigned long long accA = add2(aA0, aA1);
        unsigned long long accB = add2(aB0, aB1);
        unsigned long long tt = mul2(xx0, accA);
        fma2(tt, xx1, accB);
        unpack2(tt, v0, v1);

        sV[lc][n0] = make_float2(v0, v0);
        sV[lc][n1] = make_float2(v1, v1);

        stage  = (stage  == 2) ? 0 : stage  + 1;
        stage2 = (stage2 == 2) ? 0 : stage2 + 1;
    }

    float* out = isLeft ? g_left : g_right;
    out[c * 16 + n0] = v0;
    out[c * 16 + n1] = v1;
}

// ---------------------------------------------------------------------------
// Kernel 3: out[b][l] = sum_{m,k} left[b][m] * T[m][k][l] * right[b][k]
// ---------------------------------------------------------------------------
__global__ void __launch_bounds__(256)
combine_kernel(const float* __restrict__ T,
               float* __restrict__ out,
               int B, int NBL) {
    __shared__ float sT[4096];            // >= 16*16*NBL (NBL<=16)
    int tid = threadIdx.x;
    int tElems = 256 * NBL;
    for (int i = tid; i < tElems; i += blockDim.x) sT[i] = T[i];
    __syncthreads();

    int idx = blockIdx.x * blockDim.x + tid;
    if (idx >= B * NBL) return;
    int b = idx / NBL;
    int l = idx - b * NBL;

    float lv[16], rv[16];
#pragma unroll
    for (int k = 0; k < 16; ++k) {
        lv[k] = g_left [b * 16 + k];
        rv[k] = g_right[b * 16 + k];
    }
    float s = 0.f;
#pragma unroll
    for (int m = 0; m < 16; ++m) {
        float t = 0.f;
#pragma unroll
        for (int k = 0; k < 16; ++k)
            t = fmaf(sT[(m * 16 + k) * NBL + l], rv[k], t);
        s = fmaf(lv[m], t, s);
    }
    out[idx] = s;
}

// ---------------------------------------------------------------------------
extern "C" void kernel_launch(void* const* d_in, const int* in_sizes, int n_in,
                              void* d_out, int out_size) {
    const float* inputs  = (const float*)d_in[0];
    const float* A_left  = (const float*)d_in[1];
    const float* A_mid   = (const float*)d_in[2];
    const float* A_right = (const float*)d_in[3];
    const float* T_out   = (const float*)d_in[4];
    const int*   pos     = (const int*)d_in[5];

    int Lm2 = in_sizes[2] / 512;          // L-2 = 194
    int L   = Lm2 + 2;                    // 196
    int B   = in_sizes[0] / (2 * L);      // 2048
    int NBL = in_sizes[4] / 256;          // 10

    prep_kernel<<<(Lm2 + 1) / 2, 256>>>(A_mid, Lm2);

    // 16 chains/block per side -> 2*(B/16) blocks of 128 threads
    chain_kernel<<<B / 8, 128>>>(inputs, A_left, A_right, pos, B, L);

    int total = B * NBL;
    combine_kernel<<<(total + 255) / 256, 256>>>(T_out, (float*)d_out, B, NBL);
}